// round 7
// baseline (speedup 1.0000x reference)
#include <cuda_runtime.h>
#include <cstdint>

#define NN 100000
#define NE 1600000
#define FF 128
#define KCH 4
#define PCD 32
#define HID 128
#define NB 144            // GEMM B cols: 128 c + 8 p + 8 pad
#define SCB 1024
#define NBLK ((NN + SCB - 1) / SCB)   // 98

// ---------------- scratch ----------------
__device__ float g_c[(size_t)NN * HID];     // 51.2 MB
__device__ float g_p[(size_t)NN * 8];       // 3.2 MB
__device__ float g_w[(size_t)NE * 4];       // 25.6 MB (slot-ordered)
__device__ float g_Bfull[FF * NB];          // folded [Weff | aW1col | aW1row | 0]
__device__ float g_beff[HID];
__device__ int   g_deg[NN];
__device__ int   g_offs[NN];
__device__ int   g_rank[NE];
__device__ int   g_ecl[NE];
__device__ int   g_bsums[128];

// ---------------- prep: B = [Wlin@Wconv | aW1 halves | 0], beff ----------------
__global__ void k_prep(const float* __restrict__ Wlin,
                       const float* __restrict__ Wconv,
                       const float* __restrict__ blin,
                       const float* __restrict__ aW1) {
    int idx = blockIdx.x * blockDim.x + threadIdx.x;
    if (idx >= FF * NB) return;
    int f = idx / NB, n = idx - f * NB;
    float v = 0.f;
    if (n < 128) {
        int k = n >> 5, q = n & 31;
        const float* wl = Wlin + ((size_t)k * FF + f) * PCD;
        const float* wc = Wconv + k * PCD * PCD + q;
        float s = 0.f;
#pragma unroll
        for (int p = 0; p < PCD; p++) s += wl[p] * wc[p * PCD];
        v = s;
        if (f == 0) {
            const float* bl = blin + k * PCD;
            float b = 0.f;
#pragma unroll
            for (int p = 0; p < PCD; p++) b += bl[p] * wc[p * PCD];
            g_beff[n] = b;
        }
    } else if (n < 132) {
        v = aW1[f * 4 + (n - 128)];            // col-half
    } else if (n < 136) {
        v = aW1[(128 + f) * 4 + (n - 132)];    // row-half
    }
    g_Bfull[f * NB + n] = v;
}

__global__ void k_zero_deg() {
    int i = blockIdx.x * blockDim.x + threadIdx.x;
    if (i < NN) g_deg[i] = 0;
}

__global__ void k_hist(const int* __restrict__ row) {
    int e = blockIdx.x * blockDim.x + threadIdx.x;
    if (e < NE) g_rank[e] = atomicAdd(&g_deg[row[e]], 1);
}

// ---------------- scans ----------------
__global__ void k_scan1() {
    __shared__ int s[SCB];
    int b = blockIdx.x, t = threadIdx.x;
    int i = b * SCB + t;
    int v = (i < NN) ? g_deg[i] : 0;
    s[t] = v;
    __syncthreads();
    for (int d = 1; d < SCB; d <<= 1) {
        int tmp = (t >= d) ? s[t - d] : 0;
        __syncthreads();
        s[t] += tmp;
        __syncthreads();
    }
    if (i < NN) g_offs[i] = s[t] - v;
    if (t == SCB - 1) g_bsums[b] = s[t];
}

__global__ void k_scan2(int nb) {
    __shared__ int s[128];
    int t = threadIdx.x;
    s[t] = (t < nb) ? g_bsums[t] : 0;
    __syncthreads();
    if (t == 0) {
        int run = 0;
        for (int i = 0; i < nb; i++) { int v = s[i]; s[i] = run; run += v; }
    }
    __syncthreads();
    if (t < nb) g_bsums[t] = s[t];
}

__global__ void k_scan3() {
    int i = blockIdx.x * blockDim.x + threadIdx.x;
    if (i < NN) g_offs[i] += g_bsums[i >> 10];
}

// ---------------- tf32 helpers ----------------
__device__ __forceinline__ uint32_t f2tf32(float a) {
    uint32_t r;
    asm("cvt.rna.tf32.f32 %0, %1;" : "=r"(r) : "f"(a));
    return r;
}
__device__ __forceinline__ void mma_tf32(float* d, uint32_t a0, uint32_t a1, uint32_t b0) {
    asm volatile("mma.sync.aligned.m16n8k4.row.col.f32.tf32.tf32.f32 "
                 "{%0,%1,%2,%3}, {%4,%5}, {%6}, {%0,%1,%2,%3};\n"
                 : "+f"(d[0]), "+f"(d[1]), "+f"(d[2]), "+f"(d[3])
                 : "r"(a0), "r"(a1), "r"(b0));
}

// ---------------- GEMM: [c|p] = x @ Bfull (3xTF32 tensor core) ----------------
// block: 128 rows x 144 cols; 8 warps as 4(M) x 2(N); warp: 32 rows x 72 cols
#define APAD 36
#define BPAD 168   // 168 mod 32 == 8 -> conflict-free B frag loads
__global__ void __launch_bounds__(256) k_gemm2(const float* __restrict__ x) {
    __shared__ float As[128][APAD];       // raw fp32 x tile (chunk of K=32)
    __shared__ float Bs[32][BPAD];        // raw fp32 B chunk
    int tid = threadIdx.x;
    int wid = tid >> 5, lane = tid & 31;
    int wm = wid & 3, wn = wid >> 2;      // 4 M-warps x 2 N-warps
    int g = lane >> 2, t = lane & 3;
    int m0 = blockIdx.x * 128;

    float acc[2][9][4];
#pragma unroll
    for (int m = 0; m < 2; m++)
#pragma unroll
        for (int n = 0; n < 9; n++)
#pragma unroll
            for (int i = 0; i < 4; i++) acc[m][n][i] = 0.f;

    for (int kb0 = 0; kb0 < FF; kb0 += 32) {
        // load A chunk: 128 x 32 floats = 1024 float4
#pragma unroll
        for (int l = 0; l < 4; l++) {
            int i = tid + l * 256;
            int r = i >> 3, c4 = (i & 7) << 2;
            float4 v = make_float4(0.f, 0.f, 0.f, 0.f);
            if (m0 + r < NN) v = *(const float4*)(x + (size_t)(m0 + r) * FF + kb0 + c4);
            *(float4*)&As[r][c4] = v;
        }
        // load B chunk: 32 x 144 floats = 1152 float4
        for (int i = tid; i < 1152; i += 256) {
            int r = i / 36, c4 = (i - r * 36) << 2;
            *(float4*)&Bs[r][c4] = *(const float4*)(g_Bfull + (kb0 + r) * NB + c4);
        }
        __syncthreads();
#pragma unroll
        for (int k4 = 0; k4 < 8; k4++) {
            int kk = (k4 << 2) + t;
            uint32_t ah[2][2], al[2][2];
#pragma unroll
            for (int m = 0; m < 2; m++) {
                int r = wm * 32 + m * 16 + g;
                float a_top = As[r][kk];
                float a_bot = As[r + 8][kk];
                ah[m][0] = f2tf32(a_top);
                al[m][0] = f2tf32(a_top - __uint_as_float(ah[m][0]));
                ah[m][1] = f2tf32(a_bot);
                al[m][1] = f2tf32(a_bot - __uint_as_float(ah[m][1]));
            }
#pragma unroll
            for (int n = 0; n < 9; n++) {
                int nc = wn * 72 + n * 8 + g;
                float b = Bs[kk][nc];
                uint32_t bh = f2tf32(b);
                uint32_t bl = f2tf32(b - __uint_as_float(bh));
#pragma unroll
                for (int m = 0; m < 2; m++) {
                    mma_tf32(acc[m][n], ah[m][0], ah[m][1], bh);
                    mma_tf32(acc[m][n], al[m][0], al[m][1], bh);
                    mma_tf32(acc[m][n], ah[m][0], ah[m][1], bl);
                }
            }
        }
        __syncthreads();
    }
    // epilogue: c0,c1 -> (row, col), (row, col+1); c2,c3 -> row+8
#pragma unroll
    for (int m = 0; m < 2; m++) {
#pragma unroll
        for (int n = 0; n < 9; n++) {
            int col = wn * 72 + n * 8 + 2 * t;
            int row = m0 + wm * 32 + m * 16 + g;
            if (col < 128) {
                float2 be = *(const float2*)(g_beff + col);
                if (row < NN) {
                    float2 v = make_float2(acc[m][n][0] + be.x, acc[m][n][1] + be.y);
                    *(float2*)(g_c + (size_t)row * HID + col) = v;
                }
                if (row + 8 < NN) {
                    float2 v = make_float2(acc[m][n][2] + be.x, acc[m][n][3] + be.y);
                    *(float2*)(g_c + (size_t)(row + 8) * HID + col) = v;
                }
            } else if (col < 136) {
                int pc = col - 128;
                if (row < NN)
                    *(float2*)(g_p + (size_t)row * 8 + pc) = make_float2(acc[m][n][0], acc[m][n][1]);
                if (row + 8 < NN)
                    *(float2*)(g_p + (size_t)(row + 8) * 8 + pc) = make_float2(acc[m][n][2], acc[m][n][3]);
            }
        }
    }
}

// ---------------- fused scatter + edge softmax (writes w in CSR slot order) ----------------
__global__ void k_scat_edgew(const int* __restrict__ row, const int* __restrict__ col,
                             const float* __restrict__ ab1, const float* __restrict__ aW2,
                             const float* __restrict__ ab2) {
    int e = blockIdx.x * blockDim.x + threadIdx.x;
    if (e >= NE) return;
    int r = row[e], c = col[e];
    int slot = g_offs[r] + g_rank[e];
    g_ecl[slot] = c;
    float4 pa = *(const float4*)(g_p + (size_t)c * 8);
    float4 pb = *(const float4*)(g_p + (size_t)r * 8 + 4);
    float h[4];
    h[0] = pa.x + pb.x + __ldg(&ab1[0]);
    h[1] = pa.y + pb.y + __ldg(&ab1[1]);
    h[2] = pa.z + pb.z + __ldg(&ab1[2]);
    h[3] = pa.w + pb.w + __ldg(&ab1[3]);
    float l[4];
#pragma unroll
    for (int j = 0; j < 4; j++) {
        float s = __ldg(&ab2[j]);
#pragma unroll
        for (int k = 0; k < 4; k++) s += h[k] * __ldg(&aW2[k * 4 + j]);
        l[j] = s;
    }
    float m = fmaxf(fmaxf(l[0], l[1]), fmaxf(l[2], l[3]));
    float e0 = expf(l[0] - m), e1 = expf(l[1] - m), e2 = expf(l[2] - m), e3 = expf(l[3] - m);
    float inv = 1.f / (e0 + e1 + e2 + e3);
    *(float4*)(g_w + (size_t)slot * 4) = make_float4(e0 * inv, e1 * inv, e2 * inv, e3 * inv);
}

// ---------------- aggregation + bias + L2 norm + classifier ----------------
__global__ void __launch_bounds__(256) k_agg(const float* __restrict__ bch,
                                             const float* __restrict__ Wcls,
                                             const float* __restrict__ bcls,
                                             float* __restrict__ outH,
                                             float* __restrict__ outL,
                                             int writeLogits) {
    int wid = (blockIdx.x * blockDim.x + threadIdx.x) >> 5;
    if (wid >= NN) return;
    int lane = threadIdx.x & 31;
    int k = lane >> 3;
    int s = g_offs[wid];
    int eend = (wid == NN - 1) ? NE : g_offs[wid + 1];
    float4 acc = make_float4(0.f, 0.f, 0.f, 0.f);
    for (int j = s; j < eend; j++) {
        int cn = g_ecl[j];
        float wk = __ldg(&g_w[(size_t)j * 4 + k]);
        float4 cc = *(const float4*)(g_c + (size_t)cn * HID + lane * 4);
        acc.x += wk * cc.x; acc.y += wk * cc.y;
        acc.z += wk * cc.z; acc.w += wk * cc.w;
    }
    float4 b4 = ((const float4*)bch)[lane];
    acc.x += b4.x; acc.y += b4.y; acc.z += b4.z; acc.w += b4.w;
    float ss = acc.x * acc.x + acc.y * acc.y + acc.z * acc.z + acc.w * acc.w;
    ss += __shfl_xor_sync(0xffffffffu, ss, 1);
    ss += __shfl_xor_sync(0xffffffffu, ss, 2);
    ss += __shfl_xor_sync(0xffffffffu, ss, 4);
    float inv = 1.0f / fmaxf(sqrtf(ss), 1e-12f);
    acc.x *= inv; acc.y *= inv; acc.z *= inv; acc.w *= inv;
    ((float4*)(outH + (size_t)wid * HID))[lane] = acc;
    if (writeLogits) {
        float4 wc = ((const float4*)Wcls)[lane];
        float part = acc.x * wc.x + acc.y * wc.y + acc.z * wc.z + acc.w * wc.w;
#pragma unroll
        for (int o = 16; o; o >>= 1) part += __shfl_xor_sync(0xffffffffu, part, o);
        if (lane == 0) outL[wid] = part + __ldg(&bcls[0]);
    }
}

// ---------------- launch ----------------
extern "C" void kernel_launch(void* const* d_in, const int* in_sizes, int n_in,
                              void* d_out, int out_size) {
    const float* x    = (const float*)d_in[0];
    const int*   erow = (const int*)d_in[1];
    const int*   ecol = (const int*)d_in[2];
    const float* aW1  = (const float*)d_in[3];
    const float* ab1  = (const float*)d_in[4];
    const float* aW2  = (const float*)d_in[5];
    const float* ab2  = (const float*)d_in[6];
    const float* Wlin = (const float*)d_in[7];
    const float* blin = (const float*)d_in[8];
    const float* Wconv= (const float*)d_in[9];
    const float* bch  = (const float*)d_in[10];
    const float* Wcls = (const float*)d_in[11];
    const float* bcls = (const float*)d_in[12];
    float* out = (float*)d_out;

    k_prep<<<(FF * NB + 255) / 256, 256>>>(Wlin, Wconv, blin, aW1);
    k_zero_deg<<<(NN + 255) / 256, 256>>>();
    k_hist<<<(NE + 255) / 256, 256>>>(erow);
    k_gemm2<<<(NN + 127) / 128, 256>>>(x);
    k_scan1<<<NBLK, SCB>>>();
    k_scan2<<<1, 128>>>(NBLK);
    k_scan3<<<(NN + 255) / 256, 256>>>();
    k_scat_edgew<<<(NE + 255) / 256, 256>>>(erow, ecol, ab1, aW2, ab2);

    int writeLogits = (out_size >= NN * HID + NN) ? 1 : 0;
    k_agg<<<(NN * 32 + 255) / 256, 256>>>(bch, Wcls, bcls,
                                          out, out + (size_t)NN * HID, writeLogits);
}

// round 12
// speedup vs baseline: 1.8300x; 1.8300x over previous
#include <cuda_runtime.h>
#include <cuda_bf16.h>
#include <cstdint>

#define NN 100000
#define NE 1600000
#define FF 128
#define KCH 4
#define PCD 32
#define HID 128
#define NB 144
#define SCB 1024
#define NBLK ((NN + SCB - 1) / SCB)

// ---------------- scratch ----------------
__device__ float g_c[(size_t)NN * HID];     // 51.2 MB
__device__ float g_p[(size_t)NN * 8];       // 3.2 MB
__device__ float g_w[(size_t)NE * 4];       // 25.6 MB (slot-ordered)
__device__ __nv_bfloat16 g_Bh[4 * 144 * 40]; // B hi, chunked [chunk][n][40] (32 real k + 8 pad)
__device__ __nv_bfloat16 g_Bl[4 * 144 * 40]; // B lo
__device__ float g_beff[HID];
__device__ int   g_deg[NN];
__device__ int   g_offs[NN];
__device__ int   g_rank[NE];
__device__ int   g_ecl[NE];
__device__ int   g_bsums[128];

// ---------------- prep: fold weights, split bf16 hi/lo into chunked padded layout ----------------
__global__ void k_prep(const float* __restrict__ Wlin,
                       const float* __restrict__ Wconv,
                       const float* __restrict__ blin,
                       const float* __restrict__ aW1) {
    int idx = blockIdx.x * blockDim.x + threadIdx.x;
    if (idx >= 144 * 160) return;
    int n = idx / 160, kk = idx - n * 160;
    int chunk = kk / 40, k = kk - chunk * 40;
    int f = chunk * 32 + k;
    float v = 0.f;
    if (k < 32) {
        if (n < 128) {
            int kc = n >> 5, q = n & 31;
            const float* wl = Wlin + ((size_t)kc * FF + f) * PCD;
            const float* wc = Wconv + kc * PCD * PCD + q;
            float s = 0.f;
#pragma unroll
            for (int p = 0; p < PCD; p++) s += wl[p] * wc[p * PCD];
            v = s;
            if (f == 0) {
                const float* bl = blin + kc * PCD;
                float b = 0.f;
#pragma unroll
                for (int p = 0; p < PCD; p++) b += bl[p] * wc[p * PCD];
                g_beff[n] = b;
            }
        } else if (n < 132) {
            v = aW1[f * 4 + (n - 128)];
        } else if (n < 136) {
            v = aW1[(128 + f) * 4 + (n - 132)];
        }
    }
    __nv_bfloat16 hi = __float2bfloat16(v);
    __nv_bfloat16 lo = __float2bfloat16(v - __bfloat162float(hi));
    int off = chunk * (144 * 40) + n * 40 + k;
    g_Bh[off] = hi;
    g_Bl[off] = lo;
}

__global__ void k_zero_deg() {
    int i = blockIdx.x * blockDim.x + threadIdx.x;
    if (i < NN) g_deg[i] = 0;
}

__global__ void k_hist(const int* __restrict__ row) {
    int e = blockIdx.x * blockDim.x + threadIdx.x;
    if (e < NE) g_rank[e] = atomicAdd(&g_deg[row[e]], 1);
}

// ---------------- scans ----------------
__global__ void k_scan1() {
    __shared__ int s[SCB];
    int b = blockIdx.x, t = threadIdx.x;
    int i = b * SCB + t;
    int v = (i < NN) ? g_deg[i] : 0;
    s[t] = v;
    __syncthreads();
    for (int d = 1; d < SCB; d <<= 1) {
        int tmp = (t >= d) ? s[t - d] : 0;
        __syncthreads();
        s[t] += tmp;
        __syncthreads();
    }
    if (i < NN) g_offs[i] = s[t] - v;
    if (t == SCB - 1) g_bsums[b] = s[t];
}

__global__ void k_scan2(int nb) {
    __shared__ int s[128];
    int t = threadIdx.x;
    s[t] = (t < nb) ? g_bsums[t] : 0;
    __syncthreads();
    if (t == 0) {
        int run = 0;
        for (int i = 0; i < nb; i++) { int v = s[i]; s[i] = run; run += v; }
    }
    __syncthreads();
    if (t < nb) g_bsums[t] = s[t];
}

__global__ void k_scan3() {
    int i = blockIdx.x * blockDim.x + threadIdx.x;
    if (i < NN) g_offs[i] += g_bsums[i >> 10];
}

// ---------------- bf16 m16n8k16 mma ----------------
__device__ __forceinline__ void mma_bf16(float* d, const uint32_t* a, uint32_t b0, uint32_t b1) {
    asm volatile("mma.sync.aligned.m16n8k16.row.col.f32.bf16.bf16.f32 "
                 "{%0,%1,%2,%3}, {%4,%5,%6,%7}, {%8,%9}, {%0,%1,%2,%3};\n"
                 : "+f"(d[0]), "+f"(d[1]), "+f"(d[2]), "+f"(d[3])
                 : "r"(a[0]), "r"(a[1]), "r"(a[2]), "r"(a[3]), "r"(b0), "r"(b1));
}

// ---------------- GEMM: [c|p] = x @ B, bf16 3-term split (hh + lh + hl) ----------------
// block: 128 rows x 144 cols; warps 4(M) x 2(N); warp tile 32 x 72
__global__ void __launch_bounds__(256) k_gemm4(const float* __restrict__ x) {
    __shared__ __nv_bfloat16 Ah[128][40];
    __shared__ __nv_bfloat16 Al[128][40];
    __shared__ __nv_bfloat16 Bh[144][40];
    __shared__ __nv_bfloat16 Bl[144][40];
    int tid = threadIdx.x;
    int wid = tid >> 5, lane = tid & 31;
    int wm = wid & 3, wn = wid >> 2;
    int g = lane >> 2, t = lane & 3;
    int m0 = blockIdx.x * 128;
    int nmax = wn ? 8 : 9;   // wn=1, ntile 8 covers pad cols 136-143: skip

    float acc[2][9][4];
#pragma unroll
    for (int m = 0; m < 2; m++)
#pragma unroll
        for (int n = 0; n < 9; n++)
#pragma unroll
            for (int i = 0; i < 4; i++) acc[m][n][i] = 0.f;

    for (int ch = 0; ch < 4; ch++) {
        int k0 = ch * 32;
        // stage A chunk: 128 x 32 fp32 -> hi/lo bf16
#pragma unroll
        for (int l = 0; l < 4; l++) {
            int i = tid + l * 256;
            int r = i >> 3, c4 = (i & 7) << 2;
            float4 v = make_float4(0.f, 0.f, 0.f, 0.f);
            if (m0 + r < NN) v = *(const float4*)(x + (size_t)(m0 + r) * FF + k0 + c4);
            float f[4] = {v.x, v.y, v.z, v.w};
            __nv_bfloat16 hh[4], ll[4];
#pragma unroll
            for (int j = 0; j < 4; j++) {
                hh[j] = __float2bfloat16(f[j]);
                ll[j] = __float2bfloat16(f[j] - __bfloat162float(hh[j]));
            }
            *(uint2*)&Ah[r][c4] = *(uint2*)hh;
            *(uint2*)&Al[r][c4] = *(uint2*)ll;
        }
        // stage B chunk (pre-split, pre-padded): raw copies
        {
            const uint4* sh = (const uint4*)(g_Bh + ch * 5760);
            const uint4* sl = (const uint4*)(g_Bl + ch * 5760);
            uint4* dh = (uint4*)&Bh[0][0];
            uint4* dl = (uint4*)&Bl[0][0];
            for (int i = tid; i < 720; i += 256) {
                dh[i] = sh[i];
                dl[i] = sl[i];
            }
        }
        __syncthreads();

#pragma unroll
        for (int ks = 0; ks < 2; ks++) {
            int kk = ks << 4;
            // pass 1: Ah x Bh
            {
                uint32_t a[2][4];
#pragma unroll
                for (int m = 0; m < 2; m++) {
                    int r = wm * 32 + m * 16;
                    a[m][0] = *(const uint32_t*)&Ah[r + g][kk + 2 * t];
                    a[m][1] = *(const uint32_t*)&Ah[r + 8 + g][kk + 2 * t];
                    a[m][2] = *(const uint32_t*)&Ah[r + g][kk + 2 * t + 8];
                    a[m][3] = *(const uint32_t*)&Ah[r + 8 + g][kk + 2 * t + 8];
                }
                for (int n = 0; n < nmax; n++) {
                    int nc = wn * 72 + n * 8;
                    uint32_t b0 = *(const uint32_t*)&Bh[nc + g][kk + 2 * t];
                    uint32_t b1 = *(const uint32_t*)&Bh[nc + g][kk + 2 * t + 8];
                    mma_bf16(acc[0][n], a[0], b0, b1);
                    mma_bf16(acc[1][n], a[1], b0, b1);
                }
            }
            // pass 2: Al x Bh
            {
                uint32_t a[2][4];
#pragma unroll
                for (int m = 0; m < 2; m++) {
                    int r = wm * 32 + m * 16;
                    a[m][0] = *(const uint32_t*)&Al[r + g][kk + 2 * t];
                    a[m][1] = *(const uint32_t*)&Al[r + 8 + g][kk + 2 * t];
                    a[m][2] = *(const uint32_t*)&Al[r + g][kk + 2 * t + 8];
                    a[m][3] = *(const uint32_t*)&Al[r + 8 + g][kk + 2 * t + 8];
                }
                for (int n = 0; n < nmax; n++) {
                    int nc = wn * 72 + n * 8;
                    uint32_t b0 = *(const uint32_t*)&Bh[nc + g][kk + 2 * t];
                    uint32_t b1 = *(const uint32_t*)&Bh[nc + g][kk + 2 * t + 8];
                    mma_bf16(acc[0][n], a[0], b0, b1);
                    mma_bf16(acc[1][n], a[1], b0, b1);
                }
            }
            // pass 3: Ah x Bl
            {
                uint32_t a[2][4];
#pragma unroll
                for (int m = 0; m < 2; m++) {
                    int r = wm * 32 + m * 16;
                    a[m][0] = *(const uint32_t*)&Ah[r + g][kk + 2 * t];
                    a[m][1] = *(const uint32_t*)&Ah[r + 8 + g][kk + 2 * t];
                    a[m][2] = *(const uint32_t*)&Ah[r + g][kk + 2 * t + 8];
                    a[m][3] = *(const uint32_t*)&Ah[r + 8 + g][kk + 2 * t + 8];
                }
                for (int n = 0; n < nmax; n++) {
                    int nc = wn * 72 + n * 8;
                    uint32_t b0 = *(const uint32_t*)&Bl[nc + g][kk + 2 * t];
                    uint32_t b1 = *(const uint32_t*)&Bl[nc + g][kk + 2 * t + 8];
                    mma_bf16(acc[0][n], a[0], b0, b1);
                    mma_bf16(acc[1][n], a[1], b0, b1);
                }
            }
        }
        __syncthreads();
    }

    // epilogue (same mapping as R7): c0,c1 -> (row,col..col+1); c2,c3 -> row+8
#pragma unroll
    for (int m = 0; m < 2; m++) {
#pragma unroll
        for (int n = 0; n < 9; n++) {
            int col = wn * 72 + n * 8 + 2 * t;
            int row = m0 + wm * 32 + m * 16 + g;
            if (col < 128) {
                float2 be = *(const float2*)(g_beff + col);
                if (row < NN) {
                    float2 v = make_float2(acc[m][n][0] + be.x, acc[m][n][1] + be.y);
                    *(float2*)(g_c + (size_t)row * HID + col) = v;
                }
                if (row + 8 < NN) {
                    float2 v = make_float2(acc[m][n][2] + be.x, acc[m][n][3] + be.y);
                    *(float2*)(g_c + (size_t)(row + 8) * HID + col) = v;
                }
            } else if (col < 136) {
                int pc = col - 128;
                if (row < NN)
                    *(float2*)(g_p + (size_t)row * 8 + pc) = make_float2(acc[m][n][0], acc[m][n][1]);
                if (row + 8 < NN)
                    *(float2*)(g_p + (size_t)(row + 8) * 8 + pc) = make_float2(acc[m][n][2], acc[m][n][3]);
            }
        }
    }
}

// ---------------- fused scatter + edge softmax (writes w in CSR slot order) ----------------
__global__ void k_scat_edgew(const int* __restrict__ row, const int* __restrict__ col,
                             const float* __restrict__ ab1, const float* __restrict__ aW2,
                             const float* __restrict__ ab2) {
    int e = blockIdx.x * blockDim.x + threadIdx.x;
    if (e >= NE) return;
    int r = row[e], c = col[e];
    int slot = g_offs[r] + g_rank[e];
    g_ecl[slot] = c;
    float4 pa = *(const float4*)(g_p + (size_t)c * 8);
    float4 pb = *(const float4*)(g_p + (size_t)r * 8 + 4);
    float h[4];
    h[0] = pa.x + pb.x + __ldg(&ab1[0]);
    h[1] = pa.y + pb.y + __ldg(&ab1[1]);
    h[2] = pa.z + pb.z + __ldg(&ab1[2]);
    h[3] = pa.w + pb.w + __ldg(&ab1[3]);
    float l[4];
#pragma unroll
    for (int j = 0; j < 4; j++) {
        float s = __ldg(&ab2[j]);
#pragma unroll
        for (int k = 0; k < 4; k++) s += h[k] * __ldg(&aW2[k * 4 + j]);
        l[j] = s;
    }
    float m = fmaxf(fmaxf(l[0], l[1]), fmaxf(l[2], l[3]));
    float e0 = expf(l[0] - m), e1 = expf(l[1] - m), e2 = expf(l[2] - m), e3 = expf(l[3] - m);
    float inv = 1.f / (e0 + e1 + e2 + e3);
    *(float4*)(g_w + (size_t)slot * 4) = make_float4(e0 * inv, e1 * inv, e2 * inv, e3 * inv);
}

// ---------------- aggregation + bias + L2 norm + classifier ----------------
__global__ void __launch_bounds__(256) k_agg(const float* __restrict__ bch,
                                             const float* __restrict__ Wcls,
                                             const float* __restrict__ bcls,
                                             float* __restrict__ outH,
                                             float* __restrict__ outL,
                                             int writeLogits) {
    int wid = (blockIdx.x * blockDim.x + threadIdx.x) >> 5;
    if (wid >= NN) return;
    int lane = threadIdx.x & 31;
    int k = lane >> 3;
    int s = g_offs[wid];
    int eend = (wid == NN - 1) ? NE : g_offs[wid + 1];
    float4 acc = make_float4(0.f, 0.f, 0.f, 0.f);
    for (int j = s; j < eend; j++) {
        int cn = g_ecl[j];
        float wk = __ldg(&g_w[(size_t)j * 4 + k]);
        float4 cc = *(const float4*)(g_c + (size_t)cn * HID + lane * 4);
        acc.x += wk * cc.x; acc.y += wk * cc.y;
        acc.z += wk * cc.z; acc.w += wk * cc.w;
    }
    float4 b4 = ((const float4*)bch)[lane];
    acc.x += b4.x; acc.y += b4.y; acc.z += b4.z; acc.w += b4.w;
    float ss = acc.x * acc.x + acc.y * acc.y + acc.z * acc.z + acc.w * acc.w;
    ss += __shfl_xor_sync(0xffffffffu, ss, 1);
    ss += __shfl_xor_sync(0xffffffffu, ss, 2);
    ss += __shfl_xor_sync(0xffffffffu, ss, 4);
    float inv = 1.0f / fmaxf(sqrtf(ss), 1e-12f);
    acc.x *= inv; acc.y *= inv; acc.z *= inv; acc.w *= inv;
    ((float4*)(outH + (size_t)wid * HID))[lane] = acc;
    if (writeLogits) {
        float4 wc = ((const float4*)Wcls)[lane];
        float part = acc.x * wc.x + acc.y * wc.y + acc.z * wc.z + acc.w * wc.w;
#pragma unroll
        for (int o = 16; o; o >>= 1) part += __shfl_xor_sync(0xffffffffu, part, o);
        if (lane == 0) outL[wid] = part + __ldg(&bcls[0]);
    }
}

// ---------------- launch ----------------
extern "C" void kernel_launch(void* const* d_in, const int* in_sizes, int n_in,
                              void* d_out, int out_size) {
    const float* x    = (const float*)d_in[0];
    const int*   erow = (const int*)d_in[1];
    const int*   ecol = (const int*)d_in[2];
    const float* aW1  = (const float*)d_in[3];
    const float* ab1  = (const float*)d_in[4];
    const float* aW2  = (const float*)d_in[5];
    const float* ab2  = (const float*)d_in[6];
    const float* Wlin = (const float*)d_in[7];
    const float* blin = (const float*)d_in[8];
    const float* Wconv= (const float*)d_in[9];
    const float* bch  = (const float*)d_in[10];
    const float* Wcls = (const float*)d_in[11];
    const float* bcls = (const float*)d_in[12];
    float* out = (float*)d_out;

    k_prep<<<(144 * 160 + 255) / 256, 256>>>(Wlin, Wconv, blin, aW1);
    k_zero_deg<<<(NN + 255) / 256, 256>>>();
    k_hist<<<(NE + 255) / 256, 256>>>(erow);
    k_gemm4<<<(NN + 127) / 128, 256>>>(x);
    k_scan1<<<NBLK, SCB>>>();
    k_scan2<<<1, 128>>>(NBLK);
    k_scan3<<<(NN + 255) / 256, 256>>>();
    k_scat_edgew<<<(NE + 255) / 256, 256>>>(erow, ecol, ab1, aW2, ab2);

    int writeLogits = (out_size >= NN * HID + NN) ? 1 : 0;
    k_agg<<<(NN * 32 + 255) / 256, 256>>>(bch, Wcls, bcls,
                                          out, out + (size_t)NN * HID, writeLogits);
}

// round 13
// speedup vs baseline: 1.8303x; 1.0002x over previous
#include <cuda_runtime.h>
#include <cuda_bf16.h>
#include <cstdint>

#define NN 100000
#define NE 1600000
#define FF 128
#define KCH 4
#define PCD 32
#define HID 128
#define SCB 1024
#define NBLK ((NN + SCB - 1) / SCB)   // 98

#define HIST_BLKS 1563                // 1563*1024 >= NE
#define GEMM_BLKS 782
#define PREP_BLKS 90                  // 144*160/256
#define ZERO_BLKS 391

// ---------------- scratch ----------------
__device__ float g_c[(size_t)NN * HID];     // 51.2 MB
__device__ float g_p[(size_t)NN * 8];       // 3.2 MB
__device__ float g_w[(size_t)NE * 4];       // 25.6 MB (slot-ordered)
__device__ __nv_bfloat16 g_Bh[4 * 144 * 40];
__device__ __nv_bfloat16 g_Bl[4 * 144 * 40];
__device__ float g_beff[HID];
__device__ int   g_deg[NN];
__device__ int   g_offs[NN];
__device__ int   g_rank[NE];
__device__ int   g_ecl[NE];
__device__ int   g_bsums[128];

// ---------------- prep (blocks 0..89) + zero_deg (blocks 90..480) ----------------
__global__ void k_init(const float* __restrict__ Wlin,
                       const float* __restrict__ Wconv,
                       const float* __restrict__ blin,
                       const float* __restrict__ aW1) {
    if (blockIdx.x >= PREP_BLKS) {
        int i = (blockIdx.x - PREP_BLKS) * 256 + threadIdx.x;
        if (i < NN) g_deg[i] = 0;
        return;
    }
    int idx = blockIdx.x * blockDim.x + threadIdx.x;
    int n = idx / 160, kk = idx - n * 160;
    int chunk = kk / 40, k = kk - chunk * 40;
    int f = chunk * 32 + k;
    float v = 0.f;
    if (k < 32) {
        if (n < 128) {
            int kc = n >> 5, q = n & 31;
            const float* wl = Wlin + ((size_t)kc * FF + f) * PCD;
            const float* wc = Wconv + kc * PCD * PCD + q;
            float s = 0.f;
#pragma unroll
            for (int p = 0; p < PCD; p++) s += wl[p] * wc[p * PCD];
            v = s;
            if (f == 0) {
                const float* bl = blin + kc * PCD;
                float b = 0.f;
#pragma unroll
                for (int p = 0; p < PCD; p++) b += bl[p] * wc[p * PCD];
                g_beff[n] = b;
            }
        } else if (n < 132) {
            v = aW1[f * 4 + (n - 128)];
        } else if (n < 136) {
            v = aW1[(128 + f) * 4 + (n - 132)];
        }
    }
    __nv_bfloat16 hi = __float2bfloat16(v);
    __nv_bfloat16 lo = __float2bfloat16(v - __bfloat162float(hi));
    int off = chunk * (144 * 40) + n * 40 + k;
    g_Bh[off] = hi;
    g_Bl[off] = lo;
}

// ---------------- scans (block prefix folded into consumers; no scan3) ----------------
__global__ void k_scan1() {
    __shared__ int s[SCB];
    int b = blockIdx.x, t = threadIdx.x;
    int i = b * SCB + t;
    int v = (i < NN) ? g_deg[i] : 0;
    s[t] = v;
    __syncthreads();
    for (int d = 1; d < SCB; d <<= 1) {
        int tmp = (t >= d) ? s[t - d] : 0;
        __syncthreads();
        s[t] += tmp;
        __syncthreads();
    }
    if (i < NN) g_offs[i] = s[t] - v;
    if (t == SCB - 1) g_bsums[b] = s[t];
}

__global__ void k_scan2(int nb) {
    __shared__ int s[128];
    int t = threadIdx.x;
    s[t] = (t < nb) ? g_bsums[t] : 0;
    __syncthreads();
    if (t == 0) {
        int run = 0;
        for (int i = 0; i < nb; i++) { int v = s[i]; s[i] = run; run += v; }
    }
    __syncthreads();
    if (t < nb) g_bsums[t] = s[t];
}

// ---------------- bf16 m16n8k16 mma ----------------
__device__ __forceinline__ void mma_bf16(float* d, const uint32_t* a, uint32_t b0, uint32_t b1) {
    asm volatile("mma.sync.aligned.m16n8k16.row.col.f32.bf16.bf16.f32 "
                 "{%0,%1,%2,%3}, {%4,%5,%6,%7}, {%8,%9}, {%0,%1,%2,%3};\n"
                 : "+f"(d[0]), "+f"(d[1]), "+f"(d[2]), "+f"(d[3])
                 : "r"(a[0]), "r"(a[1]), "r"(a[2]), "r"(a[3]), "r"(b0), "r"(b1));
}

// ---------------- fused hist (blocks 0..1562) + GEMM (blocks 1563..2344) ----------------
__global__ void __launch_bounds__(256, 2) k_gemmhist(const float* __restrict__ x,
                                                     const int* __restrict__ erow) {
    if (blockIdx.x < HIST_BLKS) {
        int base = blockIdx.x * 1024 + threadIdx.x;
#pragma unroll
        for (int i = 0; i < 4; i++) {
            int e = base + i * 256;
            if (e < NE) g_rank[e] = atomicAdd(&g_deg[erow[e]], 1);
        }
        return;
    }
    __shared__ __nv_bfloat16 Ah[128][40];
    __shared__ __nv_bfloat16 Al[128][40];
    __shared__ __nv_bfloat16 Bh[144][40];
    __shared__ __nv_bfloat16 Bl[144][40];
    int tid = threadIdx.x;
    int wid = tid >> 5, lane = tid & 31;
    int wm = wid & 3, wn = wid >> 2;
    int g = lane >> 2, t = lane & 3;
    int m0 = (blockIdx.x - HIST_BLKS) * 128;
    int nmax = wn ? 8 : 9;

    float acc[2][9][4];
#pragma unroll
    for (int m = 0; m < 2; m++)
#pragma unroll
        for (int n = 0; n < 9; n++)
#pragma unroll
            for (int i = 0; i < 4; i++) acc[m][n][i] = 0.f;

    for (int ch = 0; ch < 4; ch++) {
        int k0 = ch * 32;
#pragma unroll
        for (int l = 0; l < 4; l++) {
            int i = tid + l * 256;
            int r = i >> 3, c4 = (i & 7) << 2;
            float4 v = make_float4(0.f, 0.f, 0.f, 0.f);
            if (m0 + r < NN) v = *(const float4*)(x + (size_t)(m0 + r) * FF + k0 + c4);
            float f[4] = {v.x, v.y, v.z, v.w};
            __nv_bfloat16 hh[4], ll[4];
#pragma unroll
            for (int j = 0; j < 4; j++) {
                hh[j] = __float2bfloat16(f[j]);
                ll[j] = __float2bfloat16(f[j] - __bfloat162float(hh[j]));
            }
            *(uint2*)&Ah[r][c4] = *(uint2*)hh;
            *(uint2*)&Al[r][c4] = *(uint2*)ll;
        }
        {
            const uint4* sh = (const uint4*)(g_Bh + ch * 5760);
            const uint4* sl = (const uint4*)(g_Bl + ch * 5760);
            uint4* dh = (uint4*)&Bh[0][0];
            uint4* dl = (uint4*)&Bl[0][0];
            for (int i = tid; i < 720; i += 256) {
                dh[i] = sh[i];
                dl[i] = sl[i];
            }
        }
        __syncthreads();

#pragma unroll
        for (int ks = 0; ks < 2; ks++) {
            int kk = (ks << 4) + 2 * t;
            uint32_t ah[2][4], al[2][4];
#pragma unroll
            for (int m = 0; m < 2; m++) {
                int r = wm * 32 + m * 16;
                ah[m][0] = *(const uint32_t*)&Ah[r + g][kk];
                ah[m][1] = *(const uint32_t*)&Ah[r + 8 + g][kk];
                ah[m][2] = *(const uint32_t*)&Ah[r + g][kk + 8];
                ah[m][3] = *(const uint32_t*)&Ah[r + 8 + g][kk + 8];
                al[m][0] = *(const uint32_t*)&Al[r + g][kk];
                al[m][1] = *(const uint32_t*)&Al[r + 8 + g][kk];
                al[m][2] = *(const uint32_t*)&Al[r + g][kk + 8];
                al[m][3] = *(const uint32_t*)&Al[r + 8 + g][kk + 8];
            }
            for (int n = 0; n < nmax; n++) {
                int nc = wn * 72 + n * 8 + g;
                uint32_t bh0 = *(const uint32_t*)&Bh[nc][kk];
                uint32_t bh1 = *(const uint32_t*)&Bh[nc][kk + 8];
                uint32_t bl0 = *(const uint32_t*)&Bl[nc][kk];
                uint32_t bl1 = *(const uint32_t*)&Bl[nc][kk + 8];
                mma_bf16(acc[0][n], ah[0], bh0, bh1);
                mma_bf16(acc[1][n], ah[1], bh0, bh1);
                mma_bf16(acc[0][n], al[0], bh0, bh1);
                mma_bf16(acc[1][n], al[1], bh0, bh1);
                mma_bf16(acc[0][n], ah[0], bl0, bl1);
                mma_bf16(acc[1][n], ah[1], bl0, bl1);
            }
        }
        __syncthreads();
    }

#pragma unroll
    for (int m = 0; m < 2; m++) {
#pragma unroll
        for (int n = 0; n < 9; n++) {
            int col = wn * 72 + n * 8 + 2 * t;
            int row = m0 + wm * 32 + m * 16 + g;
            if (col < 128) {
                float2 be = *(const float2*)(g_beff + col);
                if (row < NN) {
                    float2 v = make_float2(acc[m][n][0] + be.x, acc[m][n][1] + be.y);
                    *(float2*)(g_c + (size_t)row * HID + col) = v;
                }
                if (row + 8 < NN) {
                    float2 v = make_float2(acc[m][n][2] + be.x, acc[m][n][3] + be.y);
                    *(float2*)(g_c + (size_t)(row + 8) * HID + col) = v;
                }
            } else if (col < 136) {
                int pc = col - 128;
                if (row < NN)
                    *(float2*)(g_p + (size_t)row * 8 + pc) = make_float2(acc[m][n][0], acc[m][n][1]);
                if (row + 8 < NN)
                    *(float2*)(g_p + (size_t)(row + 8) * 8 + pc) = make_float2(acc[m][n][2], acc[m][n][3]);
            }
        }
    }
}

// ---------------- fused scatter + edge softmax (adds block prefix inline) ----------------
__global__ void k_scat_edgew(const int* __restrict__ row, const int* __restrict__ col,
                             const float* __restrict__ ab1, const float* __restrict__ aW2,
                             const float* __restrict__ ab2) {
    int e = blockIdx.x * blockDim.x + threadIdx.x;
    if (e >= NE) return;
    int r = row[e], c = col[e];
    int slot = g_offs[r] + __ldg(&g_bsums[r >> 10]) + g_rank[e];
    g_ecl[slot] = c;
    float4 pa = *(const float4*)(g_p + (size_t)c * 8);
    float4 pb = *(const float4*)(g_p + (size_t)r * 8 + 4);
    float h[4];
    h[0] = pa.x + pb.x + __ldg(&ab1[0]);
    h[1] = pa.y + pb.y + __ldg(&ab1[1]);
    h[2] = pa.z + pb.z + __ldg(&ab1[2]);
    h[3] = pa.w + pb.w + __ldg(&ab1[3]);
    float l[4];
#pragma unroll
    for (int j = 0; j < 4; j++) {
        float s = __ldg(&ab2[j]);
#pragma unroll
        for (int k = 0; k < 4; k++) s += h[k] * __ldg(&aW2[k * 4 + j]);
        l[j] = s;
    }
    float m = fmaxf(fmaxf(l[0], l[1]), fmaxf(l[2], l[3]));
    float e0 = expf(l[0] - m), e1 = expf(l[1] - m), e2 = expf(l[2] - m), e3 = expf(l[3] - m);
    float inv = 1.f / (e0 + e1 + e2 + e3);
    *(float4*)(g_w + (size_t)slot * 4) = make_float4(e0 * inv, e1 * inv, e2 * inv, e3 * inv);
}

// ---------------- aggregation + bias + L2 norm + classifier ----------------
__global__ void __launch_bounds__(256) k_agg(const float* __restrict__ bch,
                                             const float* __restrict__ Wcls,
                                             const float* __restrict__ bcls,
                                             float* __restrict__ outH,
                                             float* __restrict__ outL,
                                             int writeLogits) {
    int wid = (blockIdx.x * blockDim.x + threadIdx.x) >> 5;
    if (wid >= NN) return;
    int lane = threadIdx.x & 31;
    int k = lane >> 3;
    int s = g_offs[wid] + __ldg(&g_bsums[wid >> 10]);
    int eend = (wid == NN - 1) ? NE
             : (g_offs[wid + 1] + __ldg(&g_bsums[(wid + 1) >> 10]));
    float4 acc = make_float4(0.f, 0.f, 0.f, 0.f);
    int j = s;
    for (; j + 1 < eend; j += 2) {
        int cn0 = g_ecl[j];
        int cn1 = g_ecl[j + 1];
        float wk0 = __ldg(&g_w[(size_t)j * 4 + k]);
        float wk1 = __ldg(&g_w[(size_t)(j + 1) * 4 + k]);
        float4 c0 = *(const float4*)(g_c + (size_t)cn0 * HID + lane * 4);
        float4 c1 = *(const float4*)(g_c + (size_t)cn1 * HID + lane * 4);
        acc.x += wk0 * c0.x + wk1 * c1.x;
        acc.y += wk0 * c0.y + wk1 * c1.y;
        acc.z += wk0 * c0.z + wk1 * c1.z;
        acc.w += wk0 * c0.w + wk1 * c1.w;
    }
    if (j < eend) {
        int cn = g_ecl[j];
        float wk = __ldg(&g_w[(size_t)j * 4 + k]);
        float4 cc = *(const float4*)(g_c + (size_t)cn * HID + lane * 4);
        acc.x += wk * cc.x; acc.y += wk * cc.y;
        acc.z += wk * cc.z; acc.w += wk * cc.w;
    }
    float4 b4 = ((const float4*)bch)[lane];
    acc.x += b4.x; acc.y += b4.y; acc.z += b4.z; acc.w += b4.w;
    float ss = acc.x * acc.x + acc.y * acc.y + acc.z * acc.z + acc.w * acc.w;
    ss += __shfl_xor_sync(0xffffffffu, ss, 1);
    ss += __shfl_xor_sync(0xffffffffu, ss, 2);
    ss += __shfl_xor_sync(0xffffffffu, ss, 4);
    float inv = 1.0f / fmaxf(sqrtf(ss), 1e-12f);
    acc.x *= inv; acc.y *= inv; acc.z *= inv; acc.w *= inv;
    ((float4*)(outH + (size_t)wid * HID))[lane] = acc;
    if (writeLogits) {
        float4 wc = ((const float4*)Wcls)[lane];
        float part = acc.x * wc.x + acc.y * wc.y + acc.z * wc.z + acc.w * wc.w;
#pragma unroll
        for (int o = 16; o; o >>= 1) part += __shfl_xor_sync(0xffffffffu, part, o);
        if (lane == 0) outL[wid] = part + __ldg(&bcls[0]);
    }
}

// ---------------- launch ----------------
extern "C" void kernel_launch(void* const* d_in, const int* in_sizes, int n_in,
                              void* d_out, int out_size) {
    const float* x    = (const float*)d_in[0];
    const int*   erow = (const int*)d_in[1];
    const int*   ecol = (const int*)d_in[2];
    const float* aW1  = (const float*)d_in[3];
    const float* ab1  = (const float*)d_in[4];
    const float* aW2  = (const float*)d_in[5];
    const float* ab2  = (const float*)d_in[6];
    const float* Wlin = (const float*)d_in[7];
    const float* blin = (const float*)d_in[8];
    const float* Wconv= (const float*)d_in[9];
    const float* bch  = (const float*)d_in[10];
    const float* Wcls = (const float*)d_in[11];
    const float* bcls = (const float*)d_in[12];
    float* out = (float*)d_out;

    k_init<<<PREP_BLKS + ZERO_BLKS, 256>>>(Wlin, Wconv, blin, aW1);
    k_gemmhist<<<HIST_BLKS + GEMM_BLKS, 256>>>(x, erow);
    k_scan1<<<NBLK, SCB>>>();
    k_scan2<<<1, 128>>>(NBLK);
    k_scat_edgew<<<(NE + 255) / 256, 256>>>(erow, ecol, ab1, aW2, ab2);

    int writeLogits = (out_size >= NN * HID + NN) ? 1 : 0;
    k_agg<<<(NN * 32 + 255) / 256, 256>>>(bch, Wcls, bcls,
                                          out, out + (size_t)NN * HID, writeLogits);
}

// round 14
// speedup vs baseline: 1.9991x; 1.0922x over previous
#include <cuda_runtime.h>
#include <cuda_bf16.h>
#include <cuda_fp16.h>
#include <cstdint>

#define NN 100000
#define NE 1600000
#define FF 128
#define KCH 4
#define PCD 32
#define HID 128
#define SCB 1024
#define NBLK ((NN + SCB - 1) / SCB)   // 98

#define GEMM_BLKS 782
#define HIST_BLKS 1563
#define TOT_BLKS (GEMM_BLKS + HIST_BLKS)   // 2345
#define PREP_BLKS 90
#define ZERO_BLKS 391

// ---------------- scratch ----------------
__device__ __half g_c[(size_t)NN * HID];    // 25.6 MB (fp16)
__device__ float g_p[(size_t)NN * 8];       // 3.2 MB
__device__ float g_w[(size_t)NE * 4];       // 25.6 MB (slot-ordered)
__device__ __nv_bfloat16 g_Bh[4 * 144 * 40];
__device__ __nv_bfloat16 g_Bl[4 * 144 * 40];
__device__ float g_beff[HID];
__device__ int   g_deg[NN];
__device__ int   g_offs[NN];
__device__ int   g_rank[NE];
__device__ int   g_ecl[NE];
__device__ int   g_bsums[128];

// ---------------- prep (blocks 0..89) + zero_deg (rest) ----------------
__global__ void k_init(const float* __restrict__ Wlin,
                       const float* __restrict__ Wconv,
                       const float* __restrict__ blin,
                       const float* __restrict__ aW1) {
    if (blockIdx.x >= PREP_BLKS) {
        int i = (blockIdx.x - PREP_BLKS) * 256 + threadIdx.x;
        if (i < NN) g_deg[i] = 0;
        return;
    }
    int idx = blockIdx.x * blockDim.x + threadIdx.x;
    int n = idx / 160, kk = idx - n * 160;
    int chunk = kk / 40, k = kk - chunk * 40;
    int f = chunk * 32 + k;
    float v = 0.f;
    if (k < 32) {
        if (n < 128) {
            int kc = n >> 5, q = n & 31;
            const float* wl = Wlin + ((size_t)kc * FF + f) * PCD;
            const float* wc = Wconv + kc * PCD * PCD + q;
            float s = 0.f;
#pragma unroll
            for (int p = 0; p < PCD; p++) s += wl[p] * wc[p * PCD];
            v = s;
            if (f == 0) {
                const float* bl = blin + kc * PCD;
                float b = 0.f;
#pragma unroll
                for (int p = 0; p < PCD; p++) b += bl[p] * wc[p * PCD];
                g_beff[n] = b;
            }
        } else if (n < 132) {
            v = aW1[f * 4 + (n - 128)];
        } else if (n < 136) {
            v = aW1[(128 + f) * 4 + (n - 132)];
        }
    }
    __nv_bfloat16 hi = __float2bfloat16(v);
    __nv_bfloat16 lo = __float2bfloat16(v - __bfloat162float(hi));
    int off = chunk * (144 * 40) + n * 40 + k;
    g_Bh[off] = hi;
    g_Bl[off] = lo;
}

// ---------------- scans ----------------
__global__ void k_scan1() {
    __shared__ int s[SCB];
    int b = blockIdx.x, t = threadIdx.x;
    int i = b * SCB + t;
    int v = (i < NN) ? g_deg[i] : 0;
    s[t] = v;
    __syncthreads();
    for (int d = 1; d < SCB; d <<= 1) {
        int tmp = (t >= d) ? s[t - d] : 0;
        __syncthreads();
        s[t] += tmp;
        __syncthreads();
    }
    if (i < NN) g_offs[i] = s[t] - v;
    if (t == SCB - 1) g_bsums[b] = s[t];
}

__global__ void k_scan2(int nb) {
    __shared__ int s[128];
    int t = threadIdx.x;
    int v = (t < nb) ? g_bsums[t] : 0;
    s[t] = v;
    __syncthreads();
#pragma unroll
    for (int d = 1; d < 128; d <<= 1) {
        int tmp = (t >= d) ? s[t - d] : 0;
        __syncthreads();
        s[t] += tmp;
        __syncthreads();
    }
    if (t < nb) g_bsums[t] = s[t] - v;   // exclusive
}

// ---------------- bf16 m16n8k16 mma ----------------
__device__ __forceinline__ void mma_bf16(float* d, const uint32_t* a, uint32_t b0, uint32_t b1) {
    asm volatile("mma.sync.aligned.m16n8k16.row.col.f32.bf16.bf16.f32 "
                 "{%0,%1,%2,%3}, {%4,%5,%6,%7}, {%8,%9}, {%0,%1,%2,%3};\n"
                 : "+f"(d[0]), "+f"(d[1]), "+f"(d[2]), "+f"(d[3])
                 : "r"(a[0]), "r"(a[1]), "r"(a[2]), "r"(a[3]), "r"(b0), "r"(b1));
}

// ---------------- interleaved hist + GEMM: bid%3==0 -> GEMM, else hist ----------------
__global__ void __launch_bounds__(256, 2) k_gemmhist(const float* __restrict__ x,
                                                     const int* __restrict__ erow) {
    int bid = blockIdx.x;
    int q = bid / 3, r = bid - q * 3;
    if (r != 0) {
        int hb = 2 * q + (r - 1);           // 0..1562
        int base = hb * 1024 + threadIdx.x;
#pragma unroll
        for (int i = 0; i < 4; i++) {
            int e = base + i * 256;
            if (e < NE) g_rank[e] = atomicAdd(&g_deg[erow[e]], 1);
        }
        return;
    }
    __shared__ __nv_bfloat16 Ah[128][40];
    __shared__ __nv_bfloat16 Al[128][40];
    __shared__ __nv_bfloat16 Bh[144][40];
    __shared__ __nv_bfloat16 Bl[144][40];
    int tid = threadIdx.x;
    int wid = tid >> 5, lane = tid & 31;
    int wm = wid & 3, wn = wid >> 2;
    int g = lane >> 2, t = lane & 3;
    int m0 = q * 128;
    int nmax = wn ? 8 : 9;

    float acc[2][9][4];
#pragma unroll
    for (int m = 0; m < 2; m++)
#pragma unroll
        for (int n = 0; n < 9; n++)
#pragma unroll
            for (int i = 0; i < 4; i++) acc[m][n][i] = 0.f;

    for (int ch = 0; ch < 4; ch++) {
        int k0 = ch * 32;
#pragma unroll
        for (int l = 0; l < 4; l++) {
            int i = tid + l * 256;
            int rr = i >> 3, c4 = (i & 7) << 2;
            float4 v = make_float4(0.f, 0.f, 0.f, 0.f);
            if (m0 + rr < NN) v = *(const float4*)(x + (size_t)(m0 + rr) * FF + k0 + c4);
            float f[4] = {v.x, v.y, v.z, v.w};
            __nv_bfloat16 hh[4], ll[4];
#pragma unroll
            for (int j = 0; j < 4; j++) {
                hh[j] = __float2bfloat16(f[j]);
                ll[j] = __float2bfloat16(f[j] - __bfloat162float(hh[j]));
            }
            *(uint2*)&Ah[rr][c4] = *(uint2*)hh;
            *(uint2*)&Al[rr][c4] = *(uint2*)ll;
        }
        {
            const uint4* sh = (const uint4*)(g_Bh + ch * 5760);
            const uint4* sl = (const uint4*)(g_Bl + ch * 5760);
            uint4* dh = (uint4*)&Bh[0][0];
            uint4* dl = (uint4*)&Bl[0][0];
            for (int i = tid; i < 720; i += 256) {
                dh[i] = sh[i];
                dl[i] = sl[i];
            }
        }
        __syncthreads();

#pragma unroll
        for (int ks = 0; ks < 2; ks++) {
            int kk = (ks << 4) + 2 * t;
            uint32_t ah[2][4], al[2][4];
#pragma unroll
            for (int m = 0; m < 2; m++) {
                int rr = wm * 32 + m * 16;
                ah[m][0] = *(const uint32_t*)&Ah[rr + g][kk];
                ah[m][1] = *(const uint32_t*)&Ah[rr + 8 + g][kk];
                ah[m][2] = *(const uint32_t*)&Ah[rr + g][kk + 8];
                ah[m][3] = *(const uint32_t*)&Ah[rr + 8 + g][kk + 8];
                al[m][0] = *(const uint32_t*)&Al[rr + g][kk];
                al[m][1] = *(const uint32_t*)&Al[rr + 8 + g][kk];
                al[m][2] = *(const uint32_t*)&Al[rr + g][kk + 8];
                al[m][3] = *(const uint32_t*)&Al[rr + 8 + g][kk + 8];
            }
            for (int n = 0; n < nmax; n++) {
                int nc = wn * 72 + n * 8 + g;
                uint32_t bh0 = *(const uint32_t*)&Bh[nc][kk];
                uint32_t bh1 = *(const uint32_t*)&Bh[nc][kk + 8];
                uint32_t bl0 = *(const uint32_t*)&Bl[nc][kk];
                uint32_t bl1 = *(const uint32_t*)&Bl[nc][kk + 8];
                mma_bf16(acc[0][n], ah[0], bh0, bh1);
                mma_bf16(acc[1][n], ah[1], bh0, bh1);
                mma_bf16(acc[0][n], al[0], bh0, bh1);
                mma_bf16(acc[1][n], al[1], bh0, bh1);
                mma_bf16(acc[0][n], ah[0], bl0, bl1);
                mma_bf16(acc[1][n], ah[1], bl0, bl1);
            }
        }
        __syncthreads();
    }

#pragma unroll
    for (int m = 0; m < 2; m++) {
#pragma unroll
        for (int n = 0; n < 9; n++) {
            int col = wn * 72 + n * 8 + 2 * t;
            int row = m0 + wm * 32 + m * 16 + g;
            if (col < 128) {
                float2 be = *(const float2*)(g_beff + col);
                if (row < NN) {
                    *(__half2*)(g_c + (size_t)row * HID + col) =
                        __floats2half2_rn(acc[m][n][0] + be.x, acc[m][n][1] + be.y);
                }
                if (row + 8 < NN) {
                    *(__half2*)(g_c + (size_t)(row + 8) * HID + col) =
                        __floats2half2_rn(acc[m][n][2] + be.x, acc[m][n][3] + be.y);
                }
            } else if (col < 136) {
                int pc = col - 128;
                if (row < NN)
                    *(float2*)(g_p + (size_t)row * 8 + pc) = make_float2(acc[m][n][0], acc[m][n][1]);
                if (row + 8 < NN)
                    *(float2*)(g_p + (size_t)(row + 8) * 8 + pc) = make_float2(acc[m][n][2], acc[m][n][3]);
            }
        }
    }
}

// ---------------- fused scatter + edge softmax ----------------
__global__ void k_scat_edgew(const int* __restrict__ row, const int* __restrict__ col,
                             const float* __restrict__ ab1, const float* __restrict__ aW2,
                             const float* __restrict__ ab2) {
    int e = blockIdx.x * blockDim.x + threadIdx.x;
    if (e >= NE) return;
    int r = row[e], c = col[e];
    int slot = g_offs[r] + __ldg(&g_bsums[r >> 10]) + g_rank[e];
    g_ecl[slot] = c;
    float4 pa = *(const float4*)(g_p + (size_t)c * 8);
    float4 pb = *(const float4*)(g_p + (size_t)r * 8 + 4);
    float h[4];
    h[0] = pa.x + pb.x + __ldg(&ab1[0]);
    h[1] = pa.y + pb.y + __ldg(&ab1[1]);
    h[2] = pa.z + pb.z + __ldg(&ab1[2]);
    h[3] = pa.w + pb.w + __ldg(&ab1[3]);
    float l[4];
#pragma unroll
    for (int j = 0; j < 4; j++) {
        float s = __ldg(&ab2[j]);
#pragma unroll
        for (int k = 0; k < 4; k++) s += h[k] * __ldg(&aW2[k * 4 + j]);
        l[j] = s;
    }
    float m = fmaxf(fmaxf(l[0], l[1]), fmaxf(l[2], l[3]));
    float e0 = expf(l[0] - m), e1 = expf(l[1] - m), e2 = expf(l[2] - m), e3 = expf(l[3] - m);
    float inv = 1.f / (e0 + e1 + e2 + e3);
    *(float4*)(g_w + (size_t)slot * 4) = make_float4(e0 * inv, e1 * inv, e2 * inv, e3 * inv);
}

// ---------------- aggregation + bias + L2 norm + classifier (fp16 gathers) ----------------
__global__ void __launch_bounds__(256) k_agg(const float* __restrict__ bch,
                                             const float* __restrict__ Wcls,
                                             const float* __restrict__ bcls,
                                             float* __restrict__ outH,
                                             float* __restrict__ outL,
                                             int writeLogits) {
    int wid = (blockIdx.x * blockDim.x + threadIdx.x) >> 5;
    if (wid >= NN) return;
    int lane = threadIdx.x & 31;
    int k = lane >> 3;
    int s = g_offs[wid] + __ldg(&g_bsums[wid >> 10]);
    int eend = (wid == NN - 1) ? NE
             : (g_offs[wid + 1] + __ldg(&g_bsums[(wid + 1) >> 10]));
    float4 acc = make_float4(0.f, 0.f, 0.f, 0.f);
    int j = s;
    for (; j + 1 < eend; j += 2) {
        int cn0 = g_ecl[j];
        int cn1 = g_ecl[j + 1];
        float wk0 = __ldg(&g_w[(size_t)j * 4 + k]);
        float wk1 = __ldg(&g_w[(size_t)(j + 1) * 4 + k]);
        uint2 r0 = *(const uint2*)(g_c + (size_t)cn0 * HID + lane * 4);
        uint2 r1 = *(const uint2*)(g_c + (size_t)cn1 * HID + lane * 4);
        float2 a0 = __half22float2(*(__half2*)&r0.x);
        float2 a1 = __half22float2(*(__half2*)&r0.y);
        float2 b0 = __half22float2(*(__half2*)&r1.x);
        float2 b1 = __half22float2(*(__half2*)&r1.y);
        acc.x += wk0 * a0.x + wk1 * b0.x;
        acc.y += wk0 * a0.y + wk1 * b0.y;
        acc.z += wk0 * a1.x + wk1 * b1.x;
        acc.w += wk0 * a1.y + wk1 * b1.y;
    }
    if (j < eend) {
        int cn = g_ecl[j];
        float wk = __ldg(&g_w[(size_t)j * 4 + k]);
        uint2 r0 = *(const uint2*)(g_c + (size_t)cn * HID + lane * 4);
        float2 a0 = __half22float2(*(__half2*)&r0.x);
        float2 a1 = __half22float2(*(__half2*)&r0.y);
        acc.x += wk * a0.x; acc.y += wk * a0.y;
        acc.z += wk * a1.x; acc.w += wk * a1.y;
    }
    float4 b4 = ((const float4*)bch)[lane];
    acc.x += b4.x; acc.y += b4.y; acc.z += b4.z; acc.w += b4.w;
    float ss = acc.x * acc.x + acc.y * acc.y + acc.z * acc.z + acc.w * acc.w;
    ss += __shfl_xor_sync(0xffffffffu, ss, 1);
    ss += __shfl_xor_sync(0xffffffffu, ss, 2);
    ss += __shfl_xor_sync(0xffffffffu, ss, 4);
    float inv = 1.0f / fmaxf(sqrtf(ss), 1e-12f);
    acc.x *= inv; acc.y *= inv; acc.z *= inv; acc.w *= inv;
    ((float4*)(outH + (size_t)wid * HID))[lane] = acc;
    if (writeLogits) {
        float4 wc = ((const float4*)Wcls)[lane];
        float part = acc.x * wc.x + acc.y * wc.y + acc.z * wc.z + acc.w * wc.w;
#pragma unroll
        for (int o = 16; o; o >>= 1) part += __shfl_xor_sync(0xffffffffu, part, o);
        if (lane == 0) outL[wid] = part + __ldg(&bcls[0]);
    }
}

// ---------------- launch ----------------
extern "C" void kernel_launch(void* const* d_in, const int* in_sizes, int n_in,
                              void* d_out, int out_size) {
    const float* x    = (const float*)d_in[0];
    const int*   erow = (const int*)d_in[1];
    const int*   ecol = (const int*)d_in[2];
    const float* aW1  = (const float*)d_in[3];
    const float* ab1  = (const float*)d_in[4];
    const float* aW2  = (const float*)d_in[5];
    const float* ab2  = (const float*)d_in[6];
    const float* Wlin = (const float*)d_in[7];
    const float* blin = (const float*)d_in[8];
    const float* Wconv= (const float*)d_in[9];
    const float* bch  = (const float*)d_in[10];
    const float* Wcls = (const float*)d_in[11];
    const float* bcls = (const float*)d_in[12];
    float* out = (float*)d_out;

    k_init<<<PREP_BLKS + ZERO_BLKS, 256>>>(Wlin, Wconv, blin, aW1);
    k_gemmhist<<<TOT_BLKS, 256>>>(x, erow);
    k_scan1<<<NBLK, SCB>>>();
    k_scan2<<<1, 128>>>(NBLK);
    k_scat_edgew<<<(NE + 255) / 256, 256>>>(erow, ecol, ab1, aW2, ab2);

    int writeLogits = (out_size >= NN * HID + NN) ? 1 : 0;
    k_agg<<<(NN * 32 + 255) / 256, 256>>>(bch, Wcls, bcls,
                                          out, out + (size_t)NN * HID, writeLogits);
}